// round 14
// baseline (speedup 1.0000x reference)
#include <cuda_runtime.h>

#define BATCH 4
#define TLEN  4096
#define CDIM  1024
#define HDIM  64

// Scratch: q,k transposed [b][h][t]; v natural [b*t][h]
__device__ float g_qT[BATCH * HDIM * TLEN];
__device__ float g_kT[BATCH * HDIM * TLEN];
__device__ float g_v [BATCH * TLEN * HDIM];

// ---------------------------------------------------------------------------
// Projection: out = x @ W for W in {Wq, Wk, Wv}. blockIdx.y selects matrix.
// BM=64 rows, BN=64 cols (=HDIM), BK=32. 128 threads, 8x4 per-thread tile.
// y==0 (q): transposed store, pre-scaled by C^-0.5 = 1/32
// y==1 (k): transposed store
// y==2 (v): natural store
// ---------------------------------------------------------------------------
__global__ void __launch_bounds__(128)
proj_kernel(const float* __restrict__ x,
            const float* __restrict__ Wq,
            const float* __restrict__ Wk,
            const float* __restrict__ Wv)
{
    __shared__ __align__(16) float Xs[32][68];  // [k][m] (transposed x tile)
    __shared__ __align__(16) float Ws[32][68];  // [k][n]

    const int tile = blockIdx.x;          // 0..255
    const int row0 = tile * 64;           // global row (b*T + t)
    const int tid  = threadIdx.x;
    const int rg   = tid >> 4;            // 0..7  -> rows rg*8..+7
    const int cg   = tid & 15;            // 0..15 -> cols cg*4..+3

    const float* W = (blockIdx.y == 0) ? Wq : (blockIdx.y == 1) ? Wk : Wv;

    float acc[8][4];
#pragma unroll
    for (int i = 0; i < 8; i++)
#pragma unroll
        for (int j = 0; j < 4; j++) acc[i][j] = 0.f;

    for (int kc = 0; kc < CDIM; kc += 32) {
        // x tile: 64 rows x 32 cols -> Xs[k][m] (transpose on store)
        for (int l = tid; l < 512; l += 128) {        // 512 float4s
            int r  = l >> 3;                          // 0..63
            int c4 = (l & 7) << 2;                    // 0,4,..,28
            float4 f = *(const float4*)&x[(size_t)(row0 + r) * CDIM + kc + c4];
            Xs[c4 + 0][r] = f.x;
            Xs[c4 + 1][r] = f.y;
            Xs[c4 + 2][r] = f.z;
            Xs[c4 + 3][r] = f.w;
        }
        // W tile: 32 rows x 64 cols, natural
        for (int l = tid; l < 512; l += 128) {
            int r  = l >> 4;                          // 0..31
            int c4 = (l & 15) << 2;                   // 0..60
            *(float4*)&Ws[r][c4] = *(const float4*)&W[(size_t)(kc + r) * HDIM + c4];
        }
        __syncthreads();

#pragma unroll 8
        for (int k = 0; k < 32; k++) {
            float a[8], w[4];
            *(float4*)&a[0] = *(const float4*)&Xs[k][rg * 8];
            *(float4*)&a[4] = *(const float4*)&Xs[k][rg * 8 + 4];
            *(float4*)&w[0] = *(const float4*)&Ws[k][cg * 4];
#pragma unroll
            for (int i = 0; i < 8; i++)
#pragma unroll
                for (int j = 0; j < 4; j++)
                    acc[i][j] = fmaf(a[i], w[j], acc[i][j]);
        }
        __syncthreads();
    }

    if (blockIdx.y == 2) {
        // v natural: g_v[row][col]
#pragma unroll
        for (int i = 0; i < 8; i++) {
            *(float4*)&g_v[(size_t)(row0 + rg * 8 + i) * HDIM + cg * 4] =
                make_float4(acc[i][0], acc[i][1], acc[i][2], acc[i][3]);
        }
    } else {
        const float sc = (blockIdx.y == 0) ? 0.03125f : 1.0f;  // C^-0.5 = 1/32
        float* dst = (blockIdx.y == 0) ? g_qT : g_kT;
        const int b  = row0 / TLEN;
        const int t0 = row0 % TLEN;
#pragma unroll
        for (int j = 0; j < 4; j++) {
            int col = cg * 4 + j;
            float4 v0 = make_float4(acc[0][j] * sc, acc[1][j] * sc,
                                    acc[2][j] * sc, acc[3][j] * sc);
            float4 v1 = make_float4(acc[4][j] * sc, acc[5][j] * sc,
                                    acc[6][j] * sc, acc[7][j] * sc);
            size_t base = (size_t)(b * HDIM + col) * TLEN + t0 + rg * 8;
            *(float4*)&dst[base]     = v0;
            *(float4*)&dst[base + 4] = v1;
        }
    }
}

// ---------------------------------------------------------------------------
// Flash attention: BM=64 queries, BN=64 keys per iter, H=64.
// 128 threads; 8x4 register tile for both QK^T and PV. Online softmax.
// P tile overlays K tile in smem. 52KB dynamic smem -> 4 CTAs/SM.
// Grid: 256 1D blocks, bid<->bid+148 pairing sums to constant 65 work units.
// ---------------------------------------------------------------------------
#define SMSTRIDE 68
#define ATTN_SMEM (3 * 64 * SMSTRIDE * 4)

__global__ void __launch_bounds__(128)
attn_kernel(float* __restrict__ out)
{
    extern __shared__ __align__(16) float sm[];
    float* Qs = sm;                       // Qs[h*68 + r]
    float* Ks = sm + 64 * SMSTRIDE;       // Ks[h*68 + s], reused as Ps[s*68 + r]
    float* Vs = sm + 2 * 64 * SMSTRIDE;   // Vs[s*68 + d]

    // load-balanced (qt, b) assignment: pairs (u, u+148) sum to 65 units
    const int u = blockIdx.x;
    int qt, b;
    if (u < 148) { qt = 63 - (u >> 2); b = u & 3; }
    else         { int v = u - 148; qt = v >> 2; b = v & 3; }

    const int tid = threadIdx.x;
    const int rg  = tid >> 4;             // 0..7
    const int cg  = tid & 15;             // 0..15
    const int q0  = qt * 64;

    // Q tile (already transposed + scaled in g_qT)
    for (int l = tid; l < 64 * 16; l += 128) {
        int h = l >> 4, r4 = (l & 15) << 2;
        *(float4*)&Qs[h * SMSTRIDE + r4] =
            *(const float4*)&g_qT[(size_t)(b * HDIM + h) * TLEN + q0 + r4];
    }

    float m_i[8], l_i[8], O[8][4];
#pragma unroll
    for (int i = 0; i < 8; i++) {
        m_i[i] = -1e30f; l_i[i] = 0.f;
#pragma unroll
        for (int j = 0; j < 4; j++) O[i][j] = 0.f;
    }

    for (int kt = 0; kt <= qt; kt++) {
        const int k0 = kt * 64;
        __syncthreads();  // prev PV done (and Q tile ready on iter 0)

        for (int l = tid; l < 64 * 16; l += 128) {
            int h = l >> 4, s4 = (l & 15) << 2;
            *(float4*)&Ks[h * SMSTRIDE + s4] =
                *(const float4*)&g_kT[(size_t)(b * HDIM + h) * TLEN + k0 + s4];
        }
        for (int l = tid; l < 64 * 16; l += 128) {
            int s = l >> 4, d4 = (l & 15) << 2;
            *(float4*)&Vs[s * SMSTRIDE + d4] =
                *(const float4*)&g_v[(size_t)(b * TLEN + k0 + s) * HDIM + d4];
        }
        __syncthreads();

        // S = Q K^T (q pre-scaled by C^-0.5)
        float S[8][4];
#pragma unroll
        for (int i = 0; i < 8; i++)
#pragma unroll
            for (int j = 0; j < 4; j++) S[i][j] = 0.f;

#pragma unroll 8
        for (int h = 0; h < 64; h++) {
            float a[8], kk[4];
            *(float4*)&a[0]  = *(const float4*)&Qs[h * SMSTRIDE + rg * 8];
            *(float4*)&a[4]  = *(const float4*)&Qs[h * SMSTRIDE + rg * 8 + 4];
            *(float4*)&kk[0] = *(const float4*)&Ks[h * SMSTRIDE + cg * 4];
#pragma unroll
            for (int i = 0; i < 8; i++)
#pragma unroll
                for (int j = 0; j < 4; j++)
                    S[i][j] = fmaf(a[i], kk[j], S[i][j]);
        }

        // causal mask on diagonal tile
        if (kt == qt) {
#pragma unroll
            for (int i = 0; i < 8; i++)
#pragma unroll
                for (int j = 0; j < 4; j++)
                    if (cg * 4 + j > rg * 8 + i) S[i][j] = -1e30f;
        }

        // online softmax (row reduction over 16 cg lanes)
#pragma unroll
        for (int i = 0; i < 8; i++) {
            float tm = fmaxf(fmaxf(S[i][0], S[i][1]), fmaxf(S[i][2], S[i][3]));
            tm = fmaxf(tm, __shfl_xor_sync(0xffffffffu, tm, 1));
            tm = fmaxf(tm, __shfl_xor_sync(0xffffffffu, tm, 2));
            tm = fmaxf(tm, __shfl_xor_sync(0xffffffffu, tm, 4));
            tm = fmaxf(tm, __shfl_xor_sync(0xffffffffu, tm, 8));
            float mn    = fmaxf(m_i[i], tm);
            float alpha = __expf(m_i[i] - mn);
            m_i[i] = mn;
            float rs = 0.f;
#pragma unroll
            for (int j = 0; j < 4; j++) {
                S[i][j] = __expf(S[i][j] - mn);
                rs += S[i][j];
            }
            rs += __shfl_xor_sync(0xffffffffu, rs, 1);
            rs += __shfl_xor_sync(0xffffffffu, rs, 2);
            rs += __shfl_xor_sync(0xffffffffu, rs, 4);
            rs += __shfl_xor_sync(0xffffffffu, rs, 8);
            l_i[i] = l_i[i] * alpha + rs;
#pragma unroll
            for (int j = 0; j < 4; j++) O[i][j] *= alpha;
        }

        __syncthreads();  // all S reads of Ks done before overlay write
        float* Ps = Ks;   // Ps[s*68 + r] = P[r][s]
#pragma unroll
        for (int j = 0; j < 4; j++) {
            int s = cg * 4 + j;
            *(float4*)&Ps[s * SMSTRIDE + rg * 8] =
                make_float4(S[0][j], S[1][j], S[2][j], S[3][j]);
            *(float4*)&Ps[s * SMSTRIDE + rg * 8 + 4] =
                make_float4(S[4][j], S[5][j], S[6][j], S[7][j]);
        }
        __syncthreads();

        // O += P V
#pragma unroll 8
        for (int s = 0; s < 64; s++) {
            float p[8], vv[4];
            *(float4*)&p[0]  = *(const float4*)&Ps[s * SMSTRIDE + rg * 8];
            *(float4*)&p[4]  = *(const float4*)&Ps[s * SMSTRIDE + rg * 8 + 4];
            *(float4*)&vv[0] = *(const float4*)&Vs[s * SMSTRIDE + cg * 4];
#pragma unroll
            for (int i = 0; i < 8; i++)
#pragma unroll
                for (int j = 0; j < 4; j++)
                    O[i][j] = fmaf(p[i], vv[j], O[i][j]);
        }
    }

    // epilogue: out[b][t][h] = O / l
#pragma unroll
    for (int i = 0; i < 8; i++) {
        float inv = 1.0f / l_i[i];
        int row = q0 + rg * 8 + i;
        *(float4*)&out[((size_t)b * TLEN + row) * HDIM + cg * 4] =
            make_float4(O[i][0] * inv, O[i][1] * inv, O[i][2] * inv, O[i][3] * inv);
    }
}

// ---------------------------------------------------------------------------
extern "C" void kernel_launch(void* const* d_in, const int* in_sizes, int n_in,
                              void* d_out, int out_size)
{
    const float* x  = (const float*)d_in[0];
    const float* Wk = (const float*)d_in[1];
    const float* Wq = (const float*)d_in[2];
    const float* Wv = (const float*)d_in[3];
    float* out = (float*)d_out;

    cudaFuncSetAttribute(attn_kernel,
                         cudaFuncAttributeMaxDynamicSharedMemorySize, ATTN_SMEM);

    proj_kernel<<<dim3(256, 3), 128>>>(x, Wq, Wk, Wv);
    attn_kernel<<<256, 128, ATTN_SMEM>>>(out);
}

// round 17
// speedup vs baseline: 1.0031x; 1.0031x over previous
#include <cuda_runtime.h>

#define BATCH 4
#define TLEN  4096
#define CDIM  1024
#define HDIM  64

// Scratch: q,k transposed [b][h][t]; v natural [b*t][h]
__device__ float g_qT[BATCH * HDIM * TLEN];
__device__ float g_kT[BATCH * HDIM * TLEN];
__device__ float g_v [BATCH * TLEN * HDIM];

// ---------------------------------------------------------------------------
// Projection: out = x @ W for W in {Wq, Wk, Wv}. blockIdx.y selects matrix.
// BM=64 rows, BN=64 cols (=HDIM), BK=32. 128 threads, 8x4 per-thread tile.
// y==0 (q): transposed store, pre-scaled by C^-0.5 = 1/32
// y==1 (k): transposed store
// y==2 (v): natural store
// ---------------------------------------------------------------------------
__global__ void __launch_bounds__(128)
proj_kernel(const float* __restrict__ x,
            const float* __restrict__ Wq,
            const float* __restrict__ Wk,
            const float* __restrict__ Wv)
{
    __shared__ __align__(16) float Xs[32][68];  // [k][m] (transposed x tile)
    __shared__ __align__(16) float Ws[32][68];  // [k][n]

    const int tile = blockIdx.x;          // 0..255
    const int row0 = tile * 64;           // global row (b*T + t)
    const int tid  = threadIdx.x;
    const int rg   = tid >> 4;            // 0..7  -> rows rg*8..+7
    const int cg   = tid & 15;            // 0..15 -> cols cg*4..+3

    const float* W = (blockIdx.y == 0) ? Wq : (blockIdx.y == 1) ? Wk : Wv;

    float acc[8][4];
#pragma unroll
    for (int i = 0; i < 8; i++)
#pragma unroll
        for (int j = 0; j < 4; j++) acc[i][j] = 0.f;

    for (int kc = 0; kc < CDIM; kc += 32) {
        // x tile: 64 rows x 32 cols -> Xs[k][m] (transpose on store)
        for (int l = tid; l < 512; l += 128) {        // 512 float4s
            int r  = l >> 3;                          // 0..63
            int c4 = (l & 7) << 2;                    // 0,4,..,28
            float4 f = *(const float4*)&x[(size_t)(row0 + r) * CDIM + kc + c4];
            Xs[c4 + 0][r] = f.x;
            Xs[c4 + 1][r] = f.y;
            Xs[c4 + 2][r] = f.z;
            Xs[c4 + 3][r] = f.w;
        }
        // W tile: 32 rows x 64 cols, natural
        for (int l = tid; l < 512; l += 128) {
            int r  = l >> 4;                          // 0..31
            int c4 = (l & 15) << 2;                   // 0..60
            *(float4*)&Ws[r][c4] = *(const float4*)&W[(size_t)(kc + r) * HDIM + c4];
        }
        __syncthreads();

#pragma unroll 8
        for (int k = 0; k < 32; k++) {
            float a[8], w[4];
            *(float4*)&a[0] = *(const float4*)&Xs[k][rg * 8];
            *(float4*)&a[4] = *(const float4*)&Xs[k][rg * 8 + 4];
            *(float4*)&w[0] = *(const float4*)&Ws[k][cg * 4];
#pragma unroll
            for (int i = 0; i < 8; i++)
#pragma unroll
                for (int j = 0; j < 4; j++)
                    acc[i][j] = fmaf(a[i], w[j], acc[i][j]);
        }
        __syncthreads();
    }

    if (blockIdx.y == 2) {
        // v natural: g_v[row][col]
#pragma unroll
        for (int i = 0; i < 8; i++) {
            *(float4*)&g_v[(size_t)(row0 + rg * 8 + i) * HDIM + cg * 4] =
                make_float4(acc[i][0], acc[i][1], acc[i][2], acc[i][3]);
        }
    } else {
        const float sc = (blockIdx.y == 0) ? 0.03125f : 1.0f;  // C^-0.5 = 1/32
        float* dst = (blockIdx.y == 0) ? g_qT : g_kT;
        const int b  = row0 / TLEN;
        const int t0 = row0 % TLEN;
#pragma unroll
        for (int j = 0; j < 4; j++) {
            int col = cg * 4 + j;
            float4 v0 = make_float4(acc[0][j] * sc, acc[1][j] * sc,
                                    acc[2][j] * sc, acc[3][j] * sc);
            float4 v1 = make_float4(acc[4][j] * sc, acc[5][j] * sc,
                                    acc[6][j] * sc, acc[7][j] * sc);
            size_t base = (size_t)(b * HDIM + col) * TLEN + t0 + rg * 8;
            *(float4*)&dst[base]     = v0;
            *(float4*)&dst[base + 4] = v1;
        }
    }
}

// ---------------------------------------------------------------------------
// Flash attention: BM=64 queries, BN=64 keys per iter, H=64.
// 128 threads; 8x4 register tile for both QK^T and PV. Online softmax.
// P tile overlays K tile in smem. 52KB dynamic smem -> 4 CTAs/SM.
// Grid: 256 1D blocks, bid<->bid+148 pairing sums to constant 65 work units.
// ---------------------------------------------------------------------------
#define SMSTRIDE 68
#define ATTN_SMEM (3 * 64 * SMSTRIDE * 4)

__global__ void __launch_bounds__(128)
attn_kernel(float* __restrict__ out)
{
    extern __shared__ __align__(16) float sm[];
    float* Qs = sm;                       // Qs[h*68 + r]
    float* Ks = sm + 64 * SMSTRIDE;       // Ks[h*68 + s], reused as Ps[s*68 + r]
    float* Vs = sm + 2 * 64 * SMSTRIDE;   // Vs[s*68 + d]

    // load-balanced (qt, b) assignment: pairs (u, u+148) sum to 65 units
    const int u = blockIdx.x;
    int qt, b;
    if (u < 148) { qt = 63 - (u >> 2); b = u & 3; }
    else         { int v = u - 148; qt = v >> 2; b = v & 3; }

    const int tid = threadIdx.x;
    const int rg  = tid >> 4;             // 0..7
    const int cg  = tid & 15;             // 0..15
    const int q0  = qt * 64;

    // Q tile (already transposed + scaled in g_qT)
    for (int l = tid; l < 64 * 16; l += 128) {
        int h = l >> 4, r4 = (l & 15) << 2;
        *(float4*)&Qs[h * SMSTRIDE + r4] =
            *(const float4*)&g_qT[(size_t)(b * HDIM + h) * TLEN + q0 + r4];
    }

    float m_i[8], l_i[8], O[8][4];
#pragma unroll
    for (int i = 0; i < 8; i++) {
        m_i[i] = -1e30f; l_i[i] = 0.f;
#pragma unroll
        for (int j = 0; j < 4; j++) O[i][j] = 0.f;
    }

    for (int kt = 0; kt <= qt; kt++) {
        const int k0 = kt * 64;
        __syncthreads();  // prev PV done (and Q tile ready on iter 0)

        for (int l = tid; l < 64 * 16; l += 128) {
            int h = l >> 4, s4 = (l & 15) << 2;
            *(float4*)&Ks[h * SMSTRIDE + s4] =
                *(const float4*)&g_kT[(size_t)(b * HDIM + h) * TLEN + k0 + s4];
        }
        for (int l = tid; l < 64 * 16; l += 128) {
            int s = l >> 4, d4 = (l & 15) << 2;
            *(float4*)&Vs[s * SMSTRIDE + d4] =
                *(const float4*)&g_v[(size_t)(b * TLEN + k0 + s) * HDIM + d4];
        }
        __syncthreads();

        // S = Q K^T (q pre-scaled by C^-0.5)
        float S[8][4];
#pragma unroll
        for (int i = 0; i < 8; i++)
#pragma unroll
            for (int j = 0; j < 4; j++) S[i][j] = 0.f;

#pragma unroll 8
        for (int h = 0; h < 64; h++) {
            float a[8], kk[4];
            *(float4*)&a[0]  = *(const float4*)&Qs[h * SMSTRIDE + rg * 8];
            *(float4*)&a[4]  = *(const float4*)&Qs[h * SMSTRIDE + rg * 8 + 4];
            *(float4*)&kk[0] = *(const float4*)&Ks[h * SMSTRIDE + cg * 4];
#pragma unroll
            for (int i = 0; i < 8; i++)
#pragma unroll
                for (int j = 0; j < 4; j++)
                    S[i][j] = fmaf(a[i], kk[j], S[i][j]);
        }

        // causal mask on diagonal tile
        if (kt == qt) {
#pragma unroll
            for (int i = 0; i < 8; i++)
#pragma unroll
                for (int j = 0; j < 4; j++)
                    if (cg * 4 + j > rg * 8 + i) S[i][j] = -1e30f;
        }

        // online softmax (row reduction over 16 cg lanes)
#pragma unroll
        for (int i = 0; i < 8; i++) {
            float tm = fmaxf(fmaxf(S[i][0], S[i][1]), fmaxf(S[i][2], S[i][3]));
            tm = fmaxf(tm, __shfl_xor_sync(0xffffffffu, tm, 1));
            tm = fmaxf(tm, __shfl_xor_sync(0xffffffffu, tm, 2));
            tm = fmaxf(tm, __shfl_xor_sync(0xffffffffu, tm, 4));
            tm = fmaxf(tm, __shfl_xor_sync(0xffffffffu, tm, 8));
            float mn    = fmaxf(m_i[i], tm);
            float alpha = __expf(m_i[i] - mn);
            m_i[i] = mn;
            float rs = 0.f;
#pragma unroll
            for (int j = 0; j < 4; j++) {
                S[i][j] = __expf(S[i][j] - mn);
                rs += S[i][j];
            }
            rs += __shfl_xor_sync(0xffffffffu, rs, 1);
            rs += __shfl_xor_sync(0xffffffffu, rs, 2);
            rs += __shfl_xor_sync(0xffffffffu, rs, 4);
            rs += __shfl_xor_sync(0xffffffffu, rs, 8);
            l_i[i] = l_i[i] * alpha + rs;
#pragma unroll
            for (int j = 0; j < 4; j++) O[i][j] *= alpha;
        }

        __syncthreads();  // all S reads of Ks done before overlay write
        float* Ps = Ks;   // Ps[s*68 + r] = P[r][s]
#pragma unroll
        for (int j = 0; j < 4; j++) {
            int s = cg * 4 + j;
            *(float4*)&Ps[s * SMSTRIDE + rg * 8] =
                make_float4(S[0][j], S[1][j], S[2][j], S[3][j]);
            *(float4*)&Ps[s * SMSTRIDE + rg * 8 + 4] =
                make_float4(S[4][j], S[5][j], S[6][j], S[7][j]);
        }
        __syncthreads();

        // O += P V
#pragma unroll 8
        for (int s = 0; s < 64; s++) {
            float p[8], vv[4];
            *(float4*)&p[0]  = *(const float4*)&Ps[s * SMSTRIDE + rg * 8];
            *(float4*)&p[4]  = *(const float4*)&Ps[s * SMSTRIDE + rg * 8 + 4];
            *(float4*)&vv[0] = *(const float4*)&Vs[s * SMSTRIDE + cg * 4];
#pragma unroll
            for (int i = 0; i < 8; i++)
#pragma unroll
                for (int j = 0; j < 4; j++)
                    O[i][j] = fmaf(p[i], vv[j], O[i][j]);
        }
    }

    // epilogue: out[b][t][h] = O / l
#pragma unroll
    for (int i = 0; i < 8; i++) {
        float inv = 1.0f / l_i[i];
        int row = q0 + rg * 8 + i;
        *(float4*)&out[((size_t)b * TLEN + row) * HDIM + cg * 4] =
            make_float4(O[i][0] * inv, O[i][1] * inv, O[i][2] * inv, O[i][3] * inv);
    }
}

// ---------------------------------------------------------------------------
extern "C" void kernel_launch(void* const* d_in, const int* in_sizes, int n_in,
                              void* d_out, int out_size)
{
    const float* x  = (const float*)d_in[0];
    const float* Wk = (const float*)d_in[1];
    const float* Wq = (const float*)d_in[2];
    const float* Wv = (const float*)d_in[3];
    float* out = (float*)d_out;

    cudaFuncSetAttribute(attn_kernel,
                         cudaFuncAttributeMaxDynamicSharedMemorySize, ATTN_SMEM);

    proj_kernel<<<dim3(256, 3), 128>>>(x, Wq, Wk, Wv);
    attn_kernel<<<256, 128, ATTN_SMEM>>>(out);
}